// round 3
// baseline (speedup 1.0000x reference)
#include <cuda_runtime.h>

// KAConvComparision: rational (Pade) per-tap conv.
// x:      (B=4, C=16, H=64, W=64) f32
// nums:   (F=32, C=16, 3, 3, 6)   f32
// denoms: (F=32, C=16, 3, 3, 4)   f32
// out:    (B=4, F=32, H=64, W=64) f32
// out[b,f,y,x] = sum_{c,ky,kx} P_{f,c,k}(v) / (1 + |Qs_{f,c,k}(v)|),
//   v = x[b,c,y+ky-1,x+kx-1] (zero pad), P deg-5, Qs = sum_{m=1..4} b_m v^m.

#define CC 16
#define HH 64
#define WW 64
#define FF 32
#define TS_X 32      // tile width in pixels
#define TS_Y 8       // tile height
#define PPX 4        // pixels per thread (horizontal)
#define FT 4         // filters per thread
#define XS_STRIDE 35 // smem row stride (bank-conflict-free for this access pattern)

__global__ __launch_bounds__(64)
void kaconv_kernel(const float* __restrict__ x,
                   const float* __restrict__ nums,
                   const float* __restrict__ denoms,
                   float* __restrict__ out)
{
    // x tile: 16 channels x 10 rows x 34 cols (halo of 1), stride 35.
    __shared__ float xs[CC * 10 * XS_STRIDE];
    // coeff records: [c*9+k][fl] -> 12 floats (a0..a5, b1..b4, pad, pad), 16B aligned.
    __shared__ __align__(16) float cf[CC * 9 * FT * 12];

    const int tid  = threadIdx.x;
    const int tcol = blockIdx.x & 1;   // 2 col tiles
    const int trow = blockIdx.x >> 1;  // 8 row tiles
    const int fg   = blockIdx.y;       // 8 filter groups of FT=4
    const int b    = blockIdx.z;       // batch

    const int x0 = tcol * TS_X - 1;
    const int y0 = trow * TS_Y - 1;

    // ---- stage x tile (zero-padded halo matches reference semantics) ----
    for (int i = tid; i < CC * 10 * 34; i += 64) {
        int c   = i / 340;
        int rem = i - c * 340;
        int r   = rem / 34;
        int col = rem - r * 34;
        int gy = y0 + r, gx = x0 + col;
        float v = 0.0f;
        if ((unsigned)gy < (unsigned)HH && (unsigned)gx < (unsigned)WW)
            v = x[((b * CC + c) * HH + gy) * WW + gx];
        xs[c * (10 * XS_STRIDE) + r * XS_STRIDE + col] = v;
    }

    // ---- stage coefficients for this filter group ----
    // nums idx:   (f*144 + ck)*6 + j,  denoms idx: (f*144 + ck)*4 + (j-6)
    for (int i = tid; i < CC * 9 * FT * 10; i += 64) {
        int rec = i / 10;
        int j   = i - rec * 10;
        int fl  = rec & (FT - 1);
        int ck  = rec / FT;           // c*9 + k
        int f   = fg * FT + fl;
        float v;
        if (j < 6) v = nums[(f * CC * 9 + ck) * 6 + j];
        else       v = denoms[(f * CC * 9 + ck) * 4 + (j - 6)];
        cf[rec * 12 + j] = v;
    }
    __syncthreads();

    const int tx = tid & 7;   // col group (8 groups of 4 px = 32 cols)
    const int ty = tid >> 3;  // row (8 rows)

    float acc[FT][PPX];
    #pragma unroll
    for (int fl = 0; fl < FT; fl++)
        #pragma unroll
        for (int p = 0; p < PPX; p++) acc[fl][p] = 0.0f;

    for (int c = 0; c < CC; c++) {
        const float* xc = &xs[c * (10 * XS_STRIDE)];
        #pragma unroll
        for (int ky = 0; ky < 3; ky++) {
            #pragma unroll
            for (int kx = 0; kx < 3; kx++) {
                const int k = ky * 3 + kx;
                // 4 pixel values + powers (repeated multiply, like the reference)
                float xv[PPX], p2[PPX], p3[PPX], p4[PPX], p5[PPX];
                #pragma unroll
                for (int p = 0; p < PPX; p++) {
                    float v = xc[(ty + ky) * XS_STRIDE + tx * PPX + kx + p];
                    xv[p] = v;
                    p2[p] = v * v;
                    p3[p] = p2[p] * v;
                    p4[p] = p3[p] * v;
                    p5[p] = p4[p] * v;
                }
                const float4* rp = (const float4*)&cf[(c * 9 + k) * FT * 12];
                #pragma unroll
                for (int fl = 0; fl < FT; fl++) {
                    float4 c0 = rp[fl * 3 + 0];  // a0 a1 a2 a3
                    float4 c1 = rp[fl * 3 + 1];  // a4 a5 b1 b2
                    float4 c2 = rp[fl * 3 + 2];  // b3 b4 -- --
                    #pragma unroll
                    for (int p = 0; p < PPX; p++) {
                        float P = fmaf(c0.y, xv[p], c0.x);
                        P = fmaf(c0.z, p2[p], P);
                        P = fmaf(c0.w, p3[p], P);
                        P = fmaf(c1.x, p4[p], P);
                        P = fmaf(c1.y, p5[p], P);
                        float Qs = c1.z * xv[p];
                        Qs = fmaf(c1.w, p2[p], Qs);
                        Qs = fmaf(c2.x, p3[p], Qs);
                        Qs = fmaf(c2.y, p4[p], Qs);
                        float Q = 1.0f + fabsf(Qs);   // abs folds into FADD operand
                        float r;
                        asm("rcp.approx.f32 %0, %1;" : "=f"(r) : "f"(Q));
                        acc[fl][p] = fmaf(P, r, acc[fl][p]);
                    }
                }
            }
        }
    }

    // ---- write out (float4, aligned: gx base is a multiple of 4) ----
    const int gy  = trow * TS_Y + ty;
    const int gxb = tcol * TS_X + tx * PPX;
    #pragma unroll
    for (int fl = 0; fl < FT; fl++) {
        int f = fg * FT + fl;
        float4 v = make_float4(acc[fl][0], acc[fl][1], acc[fl][2], acc[fl][3]);
        *(float4*)&out[((b * FF + f) * HH + gy) * WW + gxb] = v;
    }
}

extern "C" void kernel_launch(void* const* d_in, const int* in_sizes, int n_in,
                              void* d_out, int out_size)
{
    const float* x      = (const float*)d_in[0];
    const float* nums   = (const float*)d_in[1];
    const float* denoms = (const float*)d_in[2];
    float* out          = (float*)d_out;

    dim3 grid(16, FF / FT, 4);  // (col-tiles*row-tiles, filter groups, batch)
    kaconv_kernel<<<grid, 64>>>(x, nums, denoms, out);
}

// round 4
// speedup vs baseline: 1.2295x; 1.2295x over previous
#include <cuda_runtime.h>

// KAConvComparision: rational (Pade) per-tap conv.
// x: (4,16,64,64) f32   nums: (32,16,3,3,6) f32   denoms: (32,16,3,3,4) f32
// out: (4,32,64,64) f32
// out[b,f,y,x] = sum_{c,k} P_{f,c,k}(v) / (1 + |Qs_{f,c,k}(v)|)
//
// R3 strategy: f32x2 packed math over the FILTER axis (FFMA2), Horner P/Q,
// coeffs pre-packed as filter-pairs in smem (LDS.128-native), smaller tile
// (32x4) for 1024 blocks + 6 blocks/SM (~12 warps/SM).

#define CC 16
#define HH 64
#define WW 64
#define FF 32
#define TS_X 32
#define TS_Y 4
#define XS_STRIDE 35

typedef unsigned long long u64;

__device__ __forceinline__ u64 pk2(float lo, float hi) {
    u64 r; asm("mov.b64 %0, {%1, %2};" : "=l"(r) : "f"(lo), "f"(hi)); return r;
}
__device__ __forceinline__ void upk2(u64 v, float& lo, float& hi) {
    asm("mov.b64 {%0, %1}, %2;" : "=f"(lo), "=f"(hi) : "l"(v));
}
__device__ __forceinline__ u64 fma2(u64 a, u64 b, u64 c) {
    u64 d; asm("fma.rn.f32x2 %0, %1, %2, %3;" : "=l"(d) : "l"(a), "l"(b), "l"(c)); return d;
}
__device__ __forceinline__ u64 mul2(u64 a, u64 b) {
    u64 d; asm("mul.rn.f32x2 %0, %1, %2;" : "=l"(d) : "l"(a), "l"(b)); return d;
}
__device__ __forceinline__ float rcpf(float a) {
    float r; asm("rcp.approx.f32 %0, %1;" : "=f"(r) : "f"(a)); return r;
}

__global__ __launch_bounds__(64)
void kaconv_kernel(const float* __restrict__ x,
                   const float* __restrict__ nums,
                   const float* __restrict__ denoms,
                   float* __restrict__ out)
{
    // x tile: 16 channels x 6 rows x 34 cols (halo 1), stride 35.
    __shared__ float xs[CC * 6 * XS_STRIDE];
    // coeffs: per (c*9+k, filter-pair fp): 10 packed pairs (a0..a5,b1..b4)
    // layout cf[(((ck*2)+fp)*10 + j)*2 + h], h = filter within pair. 80B/record.
    __shared__ __align__(16) float cf[CC * 9 * 2 * 20];

    const int tid  = threadIdx.x;
    const int tcol = blockIdx.x & 1;     // 2 col tiles
    const int trow = blockIdx.x >> 1;    // 16 row tiles
    const int fg   = blockIdx.y;         // 8 filter groups of 4
    const int b    = blockIdx.z;

    const int x0 = tcol * TS_X - 1;
    const int y0 = trow * TS_Y - 1;

    // ---- stage x tile (zero-padded halo) ----
    for (int i = tid; i < CC * 6 * 34; i += 64) {
        int c   = i / 204;
        int rem = i - c * 204;
        int r   = rem / 34;
        int col = rem - r * 34;
        int gy = y0 + r, gx = x0 + col;
        float v = 0.0f;
        if ((unsigned)gy < (unsigned)HH && (unsigned)gx < (unsigned)WW)
            v = x[((b * CC + c) * HH + gy) * WW + gx];
        xs[c * (6 * XS_STRIDE) + r * XS_STRIDE + col] = v;
    }

    // ---- stage coefficients, pre-packed as filter pairs ----
    for (int i = tid; i < CC * 9 * 2 * 20; i += 64) {
        int h   = i & 1;          // filter within pair
        int t   = i >> 1;
        int j   = t % 10;         // coeff index: 0..5 = a0..a5, 6..9 = b1..b4
        int rec = t / 10;
        int fp  = rec & 1;        // filter pair within group
        int ck  = rec >> 1;       // c*9 + k
        int f   = fg * 4 + fp * 2 + h;
        float v;
        if (j < 6) v = nums[(f * CC * 9 + ck) * 6 + j];
        else       v = denoms[(f * CC * 9 + ck) * 4 + (j - 6)];
        cf[i] = v;
    }
    __syncthreads();

    const int tx = tid & 15;   // 16 col groups of 2 px
    const int ty = tid >> 4;   // 4 rows

    float acc[4][2];
    #pragma unroll
    for (int fl = 0; fl < 4; fl++) { acc[fl][0] = 0.0f; acc[fl][1] = 0.0f; }

    #pragma unroll 1
    for (int c = 0; c < CC; c++) {
        const float* xc = &xs[c * (6 * XS_STRIDE)];
        #pragma unroll
        for (int ky = 0; ky < 3; ky++) {
            #pragma unroll
            for (int kx = 0; kx < 3; kx++) {
                const int k = ky * 3 + kx;
                float v0 = xc[(ty + ky) * XS_STRIDE + tx * 2 + kx + 0];
                float v1 = xc[(ty + ky) * XS_STRIDE + tx * 2 + kx + 1];
                u64 vv[2];
                vv[0] = pk2(v0, v0);
                vv[1] = pk2(v1, v1);
                const ulonglong2* cp =
                    (const ulonglong2*)&cf[(c * 9 + k) * 40];
                #pragma unroll
                for (int fp = 0; fp < 2; fp++) {
                    ulonglong2 q0 = cp[fp * 5 + 0];  // {a0,a1} pairs
                    ulonglong2 q1 = cp[fp * 5 + 1];  // {a2,a3}
                    ulonglong2 q2 = cp[fp * 5 + 2];  // {a4,a5}
                    ulonglong2 q3 = cp[fp * 5 + 3];  // {b1,b2}
                    ulonglong2 q4 = cp[fp * 5 + 4];  // {b3,b4}
                    #pragma unroll
                    for (int p = 0; p < 2; p++) {
                        u64 w = vv[p];
                        // P = a0 + v(a1 + v(a2 + v(a3 + v(a4 + v a5))))
                        u64 P = fma2(q2.y, w, q2.x);
                        P = fma2(P, w, q1.y);
                        P = fma2(P, w, q1.x);
                        P = fma2(P, w, q0.y);
                        P = fma2(P, w, q0.x);
                        // Qs = v(b1 + v(b2 + v(b3 + v b4)))
                        u64 T = fma2(q4.y, w, q4.x);
                        T = fma2(T, w, q3.y);
                        T = fma2(T, w, q3.x);
                        u64 Qs = mul2(T, w);
                        float ql, qh, pl, ph;
                        upk2(Qs, ql, qh);
                        upk2(P, pl, ph);
                        float r0 = rcpf(1.0f + fabsf(ql));
                        float r1 = rcpf(1.0f + fabsf(qh));
                        acc[fp * 2 + 0][p] = fmaf(pl, r0, acc[fp * 2 + 0][p]);
                        acc[fp * 2 + 1][p] = fmaf(ph, r1, acc[fp * 2 + 1][p]);
                    }
                }
            }
        }
    }

    // ---- write out (float2, 8B aligned: gxb even) ----
    const int gy  = trow * TS_Y + ty;
    const int gxb = tcol * TS_X + tx * 2;
    #pragma unroll
    for (int fl = 0; fl < 4; fl++) {
        int f = fg * 4 + fl;
        float2 v = make_float2(acc[fl][0], acc[fl][1]);
        *(float2*)&out[((b * FF + f) * HH + gy) * WW + gxb] = v;
    }
}

extern "C" void kernel_launch(void* const* d_in, const int* in_sizes, int n_in,
                              void* d_out, int out_size)
{
    const float* x      = (const float*)d_in[0];
    const float* nums   = (const float*)d_in[1];
    const float* denoms = (const float*)d_in[2];
    float* out          = (float*)d_out;

    dim3 grid(32, FF / 4, 4);  // (2 col x 16 row tiles, 8 filter groups, batch)
    kaconv_kernel<<<grid, 64>>>(x, nums, denoms, out);
}

// round 5
// speedup vs baseline: 1.6244x; 1.3212x over previous
#include <cuda_runtime.h>

// KAConvComparision: rational (Pade) per-tap conv.
// x: (4,16,64,64) f32   nums: (32,16,3,3,6) f32   denoms: (32,16,3,3,4) f32
// out: (4,32,64,64) f32
// out[b,f,y,x] = sum_{c,k} P_{f,c,k}(v) / (1 + |Qs_{f,c,k}(v)|)
//
// R5: occupancy-first reshape. FT=2 (one packed filter pair), PPX=2,
// blockDim=128, tile 32x8. smem 33.3KB -> 6 blocks/SM = 24 warps/SM.
// FFMA2 Horner core unchanged. xv via float2 LDS amortized over ky row.

#define CC 16
#define HH 64
#define WW 64
#define FF 32
#define TS_X 32
#define TS_Y 8
#define XR   10          // tile rows + halo
#define XW   34          // tile cols + halo (even -> float2 aligned)

typedef unsigned long long u64;

__device__ __forceinline__ u64 pk2(float lo, float hi) {
    u64 r; asm("mov.b64 %0, {%1, %2};" : "=l"(r) : "f"(lo), "f"(hi)); return r;
}
__device__ __forceinline__ void upk2(u64 v, float& lo, float& hi) {
    asm("mov.b64 {%0, %1}, %2;" : "=f"(lo), "=f"(hi) : "l"(v));
}
__device__ __forceinline__ u64 fma2(u64 a, u64 b, u64 c) {
    u64 d; asm("fma.rn.f32x2 %0, %1, %2, %3;" : "=l"(d) : "l"(a), "l"(b), "l"(c)); return d;
}
__device__ __forceinline__ u64 mul2(u64 a, u64 b) {
    u64 d; asm("mul.rn.f32x2 %0, %1, %2;" : "=l"(d) : "l"(a), "l"(b)); return d;
}
__device__ __forceinline__ float rcpf(float a) {
    float r; asm("rcp.approx.f32 %0, %1;" : "=f"(r) : "f"(a)); return r;
}

__global__ __launch_bounds__(128)
void kaconv_kernel(const float* __restrict__ x,
                   const float* __restrict__ nums,
                   const float* __restrict__ denoms,
                   float* __restrict__ out)
{
    // x tile: 16 ch x 10 rows x 34 cols, stride 34 (even: float2-aligned).
    __shared__ float xs[CC * XR * XW];                    // 21.76 KB
    // coeffs for ONE filter pair: cf[(ck*10 + j)*2 + h], 80B per (c,k) record.
    __shared__ __align__(16) float cf[CC * 9 * 10 * 2];   // 11.52 KB

    const int tid  = threadIdx.x;
    const int tcol = blockIdx.x & 1;      // 2 col tiles
    const int trow = blockIdx.x >> 1;     // 8 row tiles
    const int fp   = blockIdx.y;          // 16 filter pairs
    const int b    = blockIdx.z;

    const int x0 = tcol * TS_X - 1;
    const int y0 = trow * TS_Y - 1;

    // ---- stage x tile (zero-padded halo) ----
    for (int i = tid; i < CC * XR * XW; i += 128) {
        int c   = i / (XR * XW);
        int rem = i - c * (XR * XW);
        int r   = rem / XW;
        int col = rem - r * XW;
        int gy = y0 + r, gx = x0 + col;
        float v = 0.0f;
        if ((unsigned)gy < (unsigned)HH && (unsigned)gx < (unsigned)WW)
            v = x[((b * CC + c) * HH + gy) * WW + gx];
        xs[i] = v;
    }

    // ---- stage packed coefficient pairs for this filter pair ----
    for (int i = tid; i < CC * 9 * 20; i += 128) {
        int h  = i & 1;            // filter within pair
        int t  = i >> 1;
        int j  = t % 10;           // 0..5 = a0..a5, 6..9 = b1..b4
        int ck = t / 10;           // c*9 + k
        int f  = fp * 2 + h;
        float v;
        if (j < 6) v = nums[(f * CC * 9 + ck) * 6 + j];
        else       v = denoms[(f * CC * 9 + ck) * 4 + (j - 6)];
        cf[i] = v;
    }
    __syncthreads();

    const int tx = tid & 15;    // 16 col groups of 2 px
    const int ty = tid >> 4;    // 8 rows

    float acc00 = 0.0f, acc01 = 0.0f, acc10 = 0.0f, acc11 = 0.0f;

    // per-thread fixed bases: inner offsets become compile-time immediates
    const float* xb = &xs[ty * XW + tx * 2];
    const ulonglong2* cb = (const ulonglong2*)cf;

    #pragma unroll 1
    for (int c = 0; c < CC; c++) {
        const float* xc = xb + c * (XR * XW);
        const ulonglong2* cc_ = cb + c * (9 * 20 / 4);   // 9 records x 5 u2
        #pragma unroll
        for (int ky = 0; ky < 3; ky++) {
            // 4 consecutive cols for this row: covers kx 0..2, p 0..1
            float2 A  = *(const float2*)(xc + ky * XW);
            float2 Bv = *(const float2*)(xc + ky * XW + 2);
            float col4[4] = {A.x, A.y, Bv.x, Bv.y};
            #pragma unroll
            for (int kx = 0; kx < 3; kx++) {
                const ulonglong2* cp = cc_ + (ky * 3 + kx) * 5;
                ulonglong2 q0 = cp[0];  // {a0,a1}
                ulonglong2 q1 = cp[1];  // {a2,a3}
                ulonglong2 q2 = cp[2];  // {a4,a5}
                ulonglong2 q3 = cp[3];  // {b1,b2}
                ulonglong2 q4 = cp[4];  // {b3,b4}
                u64 vv0 = pk2(col4[kx],     col4[kx]);
                u64 vv1 = pk2(col4[kx + 1], col4[kx + 1]);
                // pixel 0
                {
                    u64 w = vv0;
                    u64 P = fma2(q2.y, w, q2.x);
                    P = fma2(P, w, q1.y);
                    P = fma2(P, w, q1.x);
                    P = fma2(P, w, q0.y);
                    P = fma2(P, w, q0.x);
                    u64 T = fma2(q4.y, w, q4.x);
                    T = fma2(T, w, q3.y);
                    T = fma2(T, w, q3.x);
                    u64 Qs = mul2(T, w);
                    float ql, qh, pl, ph;
                    upk2(Qs, ql, qh);
                    upk2(P, pl, ph);
                    float r0 = rcpf(1.0f + fabsf(ql));
                    float r1 = rcpf(1.0f + fabsf(qh));
                    acc00 = fmaf(pl, r0, acc00);
                    acc10 = fmaf(ph, r1, acc10);
                }
                // pixel 1
                {
                    u64 w = vv1;
                    u64 P = fma2(q2.y, w, q2.x);
                    P = fma2(P, w, q1.y);
                    P = fma2(P, w, q1.x);
                    P = fma2(P, w, q0.y);
                    P = fma2(P, w, q0.x);
                    u64 T = fma2(q4.y, w, q4.x);
                    T = fma2(T, w, q3.y);
                    T = fma2(T, w, q3.x);
                    u64 Qs = mul2(T, w);
                    float ql, qh, pl, ph;
                    upk2(Qs, ql, qh);
                    upk2(P, pl, ph);
                    float r0 = rcpf(1.0f + fabsf(ql));
                    float r1 = rcpf(1.0f + fabsf(qh));
                    acc01 = fmaf(pl, r0, acc01);
                    acc11 = fmaf(ph, r1, acc11);
                }
            }
        }
    }

    // ---- write out (float2, gxb even) ----
    const int gy  = trow * TS_Y + ty;
    const int gxb = tcol * TS_X + tx * 2;
    const int f0  = fp * 2;
    *(float2*)&out[((b * FF + f0    ) * HH + gy) * WW + gxb] = make_float2(acc00, acc01);
    *(float2*)&out[((b * FF + f0 + 1) * HH + gy) * WW + gxb] = make_float2(acc10, acc11);
}

extern "C" void kernel_launch(void* const* d_in, const int* in_sizes, int n_in,
                              void* d_out, int out_size)
{
    const float* x      = (const float*)d_in[0];
    const float* nums   = (const float*)d_in[1];
    const float* denoms = (const float*)d_in[2];
    float* out          = (float*)d_out;

    dim3 grid(16, FF / 2, 4);   // (2 col x 8 row tiles, 16 filter pairs, batch)
    kaconv_kernel<<<grid, 128>>>(x, nums, denoms, out);
}